// round 12
// baseline (speedup 1.0000x reference)
#include <cuda_runtime.h>
#include <cuda_fp16.h>
#include <math.h>
#include <stdint.h>

#define B_ROWS 2048
#define GIN    128
#define GH     128
#define NE     8
#define XDIM   512

// Static scratch (allocation-free rule)
__device__ __align__(16) float  g_gate[B_ROWS * NE];
__device__ __align__(16) __half g_xt[(size_t)B_ROWS * XDIM];           // fp16 activations
__device__ __align__(16) __half g_alpha[(size_t)NE * XDIM * XDIM];     // fp16 weights (4 MB)
__device__ __align__(16) float  g_part[2ull * B_ROWS * XDIM];          // ksplit partials (8 MB)

__device__ __forceinline__ float eluf(float x) { return x > 0.0f ? x : expm1f(x); }

// ---------------------------------------------------------------------------
// Gating network (validated R1-R8)
// ---------------------------------------------------------------------------
__global__ __launch_bounds__(128) void gating_kernel(
    const float* __restrict__ GI,
    const float* __restrict__ Wg0, const float* __restrict__ bg0,
    const float* __restrict__ Wg1, const float* __restrict__ bg1,
    const float* __restrict__ Wgo, const float* __restrict__ bgo)
{
    __shared__ float sx[8][GIN];
    __shared__ float sh[8][GH];
    __shared__ float sl[8][NE];

    const int r0  = blockIdx.x * 8;
    const int tid = threadIdx.x;

    for (int idx = tid; idx < 8 * GIN; idx += 128)
        sx[idx >> 7][idx & 127] = GI[(size_t)(r0 + (idx >> 7)) * GIN + (idx & 127)];
    __syncthreads();

    float acc[8];
    #pragma unroll
    for (int r = 0; r < 8; r++) acc[r] = bg0[tid];
    #pragma unroll 4
    for (int i = 0; i < GIN; i++) {
        float w = Wg0[i * GH + tid];
        #pragma unroll
        for (int r = 0; r < 8; r++) acc[r] += sx[r][i] * w;
    }
    #pragma unroll
    for (int r = 0; r < 8; r++) sh[r][tid] = eluf(acc[r]);
    __syncthreads();

    #pragma unroll
    for (int r = 0; r < 8; r++) acc[r] = bg1[tid];
    #pragma unroll 4
    for (int i = 0; i < GH; i++) {
        float w = Wg1[i * GH + tid];
        #pragma unroll
        for (int r = 0; r < 8; r++) acc[r] += sh[r][i] * w;
    }
    __syncthreads();
    #pragma unroll
    for (int r = 0; r < 8; r++) sx[r][tid] = eluf(acc[r]);
    __syncthreads();

    if (tid < 64) {
        const int r = tid >> 3, e = tid & 7;
        float a = bgo[e];
        #pragma unroll 4
        for (int i = 0; i < GH; i++) a += sx[r][i] * Wgo[i * NE + e];
        sl[r][e] = a;
    }
    __syncthreads();

    if (tid < 8) {
        const int r = tid;
        float mx = sl[r][0];
        #pragma unroll
        for (int e = 1; e < NE; e++) mx = fmaxf(mx, sl[r][e]);
        float ex[NE], s = 0.0f;
        #pragma unroll
        for (int e = 0; e < NE; e++) { ex[e] = expf(sl[r][e] - mx); s += ex[e]; }
        float inv = 1.0f / s;
        #pragma unroll
        for (int e = 0; e < NE; e++)
            g_gate[(size_t)(r0 + r) * NE + e] = ex[e] * inv;
    }
}

// float -> half conversion (8 elems per thread-iter)
__global__ __launch_bounds__(256) void cvt_half_kernel(
    const float* __restrict__ src, __half* __restrict__ dst, int n8)
{
    for (int i = blockIdx.x * 256 + threadIdx.x; i < n8; i += gridDim.x * 256) {
        float4 v0 = ((const float4*)src)[2 * i];
        float4 v1 = ((const float4*)src)[2 * i + 1];
        __half2 h[4];
        h[0] = __floats2half2_rn(v0.x, v0.y);
        h[1] = __floats2half2_rn(v0.z, v0.w);
        h[2] = __floats2half2_rn(v1.x, v1.y);
        h[3] = __floats2half2_rn(v1.z, v1.w);
        ((uint4*)dst)[i] = *(uint4*)h;
    }
}

// ---------------------------------------------------------------------------
// fp16 GEMM: each CTA covers 4 experts (z in {0,1}), single acc set with
// exact gate-ratio rescale at the 3 expert boundaries (telescoping product).
// Tile 64x64, 4 warps, warptile 32x32, BK=64 halves, NST=2 cp.async.
// ---------------------------------------------------------------------------
#define BM 64
#define BN 64
#define BKH 64
#define NKT 32                         // 4 experts * 512 / 64
#define PADH 72                        // half stride per row (144 B)
#define STG_H ((BM + BN) * PADH)       // 9216 halves per stage
#define STG_B (STG_H * 2)              // 18432 B
#define NST 2
#define SMEM_BYTES (NST * STG_B + (BM * 4 + 4 * BN) * 4)   // 38912

__device__ __forceinline__ void cp16(uint32_t dst, const void* src) {
    asm volatile("cp.async.cg.shared.global [%0], [%1], 16;"
                 :: "r"(dst), "l"(__cvta_generic_to_global(src)) : "memory");
}
__device__ __forceinline__ void ldmx4(uint32_t* r, uint32_t addr) {
    asm volatile("ldmatrix.sync.aligned.m8n8.x4.shared.b16 {%0,%1,%2,%3}, [%4];"
                 : "=r"(r[0]), "=r"(r[1]), "=r"(r[2]), "=r"(r[3]) : "r"(addr));
}
__device__ __forceinline__ void mma16(float* c, const uint32_t* a, const uint32_t* b) {
    asm volatile(
        "mma.sync.aligned.m16n8k16.row.col.f32.f16.f16.f32 "
        "{%0,%1,%2,%3}, {%4,%5,%6,%7}, {%8,%9}, {%0,%1,%2,%3};"
        : "+f"(c[0]), "+f"(c[1]), "+f"(c[2]), "+f"(c[3])
        : "r"(a[0]), "r"(a[1]), "r"(a[2]), "r"(a[3]), "r"(b[0]), "r"(b[1]));
}

__global__ __launch_bounds__(128, 4) void gemm_kernel(const float* __restrict__ beta)
{
    extern __shared__ __half smem[];
    float* sg    = (float*)(smem + NST * STG_H);   // [64][4] gates (4 experts)
    float* sbeta = sg + BM * 4;                    // [4][64]

    const int tid  = threadIdx.x;
    const int wid  = tid >> 5, lane = tid & 31;
    const int qid  = lane >> 2, qk = lane & 3;
    const int wm   = (wid & 1) * 32;
    const int wn   = (wid >> 1) * 32;
    const int n0   = blockIdx.x * BN;
    const int m0   = blockIdx.y * BM;
    const int e0   = blockIdx.z * 4;

    const uint32_t smem_u = (uint32_t)__cvta_generic_to_shared(smem);

    const int lr   = lane & 15;
    const int lkB8 = (lane >> 4) * 8;

    auto load_chunk = [&](int s, int c) {
        const int el = c >> 3;
        const int i0 = (c & 7) * BKH;
        const __half* Ab = g_xt + (size_t)m0 * XDIM + i0;
        const __half* Bb = g_alpha + ((size_t)(e0 + el) * XDIM + n0) * XDIM + i0;
        const uint32_t sa  = smem_u + s * STG_B;
        const uint32_t sbm = sa + BM * PADH * 2;
        #pragma unroll
        for (int i = 0; i < 4; i++) {          // A: 64 rows x 8 x16B
            int unit = i * 128 + tid;
            int row = unit >> 3, c16 = unit & 7;
            cp16(sa + row * (PADH * 2) + c16 * 16, Ab + (size_t)row * XDIM + c16 * 8);
        }
        #pragma unroll
        for (int i = 0; i < 4; i++) {          // B: 64 rows x 8 x16B
            int unit = i * 128 + tid;
            int row = unit >> 3, c16 = unit & 7;
            cp16(sbm + row * (PADH * 2) + c16 * 16, Bb + (size_t)row * XDIM + c16 * 8);
        }
    };

    load_chunk(0, 0);
    asm volatile("cp.async.commit_group;" ::: "memory");
    load_chunk(1, 1);
    asm volatile("cp.async.commit_group;" ::: "memory");

    if (tid < 64)   // 4 gates per row = one float4 (e0 is 0 or 4)
        *(float4*)(sg + tid * 4) =
            ((const float4*)g_gate)[(size_t)(m0 + tid) * 2 + blockIdx.z];
    for (int i = tid; i < 4 * BN; i += 128)
        sbeta[i] = beta[(size_t)(e0 + (i >> 6)) * XDIM + n0 + (i & 63)];

    float c[2][4][4];
    #pragma unroll
    for (int mt = 0; mt < 2; mt++)
        #pragma unroll
        for (int nt = 0; nt < 4; nt++)
            #pragma unroll
            for (int j = 0; j < 4; j++) c[mt][nt][j] = 0.0f;

    // hoisted per-lane fragment base offsets (bytes)
    const uint32_t aOff = ((wm + lr) * PADH + lkB8) * 2;
    const uint32_t bOff = ((wn + lr) * PADH + lkB8) * 2 + BM * PADH * 2;

    for (int kt = 0; kt < NKT; kt++) {
        asm volatile("cp.async.wait_group 1;" ::: "memory");
        __syncthreads();

        const uint32_t stg = smem_u + (kt & 1) * STG_B;
        const uint32_t aB = stg + aOff;
        const uint32_t bB = stg + bOff;

        #pragma unroll
        for (int ks = 0; ks < 4; ks++) {
            uint32_t a[2][4], b[4][2];
            #pragma unroll
            for (int mt = 0; mt < 2; mt++)
                ldmx4(a[mt], aB + (mt * 16 * PADH + ks * 16) * 2);
            #pragma unroll
            for (int p = 0; p < 2; p++) {
                uint32_t r[4];
                ldmx4(r, bB + (p * 16 * PADH + ks * 16) * 2);
                b[2 * p][0]     = r[0]; b[2 * p + 1][0] = r[1];
                b[2 * p][1]     = r[2]; b[2 * p + 1][1] = r[3];
            }
            #pragma unroll
            for (int mt = 0; mt < 2; mt++)
                #pragma unroll
                for (int nt = 0; nt < 4; nt++)
                    mma16(c[mt][nt], a[mt], b[nt]);
        }

        if ((kt & 7) == 7 && kt < NKT - 1) {   // expert boundary: c *= g_el/g_{el+1}
            const int el = kt >> 3;
            #pragma unroll
            for (int mt = 0; mt < 2; mt++) {
                const int r0 = wm + mt * 16 + qid, r1 = r0 + 8;
                const float t0 = sg[r0 * 4 + el] / sg[r0 * 4 + el + 1];
                const float t1 = sg[r1 * 4 + el] / sg[r1 * 4 + el + 1];
                #pragma unroll
                for (int nt = 0; nt < 4; nt++) {
                    c[mt][nt][0] *= t0; c[mt][nt][1] *= t0;
                    c[mt][nt][2] *= t1; c[mt][nt][3] *= t1;
                }
            }
        }

        __syncthreads();
        if (kt + 2 < NKT) load_chunk(kt & 1, kt + 2);
        asm volatile("cp.async.commit_group;" ::: "memory");
    }

    // epilogue -> partial buffer: out = g3 * c + sum_e g_e * beta_e
    float* P = g_part + (size_t)blockIdx.z * B_ROWS * XDIM;
    #pragma unroll
    for (int mt = 0; mt < 2; mt++) {
        const int r0 = wm + mt * 16 + qid, r1 = r0 + 8;
        float g0[4], g1[4];
        *(float4*)g0 = *(float4*)(sg + r0 * 4);
        *(float4*)g1 = *(float4*)(sg + r1 * 4);
        #pragma unroll
        for (int nt = 0; nt < 4; nt++) {
            const int cc = wn + nt * 8 + 2 * qk;
            float b0x = 0.f, b0y = 0.f, b1x = 0.f, b1y = 0.f;
            #pragma unroll
            for (int e = 0; e < 4; e++) {
                const float sx = sbeta[e * BN + cc], sy = sbeta[e * BN + cc + 1];
                b0x += g0[e] * sx; b0y += g0[e] * sy;
                b1x += g1[e] * sx; b1y += g1[e] * sy;
            }
            float2 o0, o1;
            o0.x = g0[3] * c[mt][nt][0] + b0x;
            o0.y = g0[3] * c[mt][nt][1] + b0y;
            o1.x = g1[3] * c[mt][nt][2] + b1x;
            o1.y = g1[3] * c[mt][nt][3] + b1y;
            *(float2*)(P + (size_t)(m0 + r0) * XDIM + n0 + cc) = o0;
            *(float2*)(P + (size_t)(m0 + r1) * XDIM + n0 + cc) = o1;
        }
    }
}

// Sum 2 partials; mode 1: ELU -> half -> g_xt; mode 0: raw fp32 -> dst
__global__ __launch_bounds__(256) void reduce_kernel(float* __restrict__ dst, int mode)
{
    const int n4 = B_ROWS * XDIM / 4;
    const float4* p0 = (const float4*)g_part;
    const float4* p1 = (const float4*)(g_part + (size_t)B_ROWS * XDIM);
    for (int i = blockIdx.x * 256 + threadIdx.x; i < n4; i += gridDim.x * 256) {
        float4 a = p0[i], b = p1[i];
        float4 v;
        v.x = a.x + b.x; v.y = a.y + b.y; v.z = a.z + b.z; v.w = a.w + b.w;
        if (mode == 1) {
            __half2 h[2];
            h[0] = __floats2half2_rn(eluf(v.x), eluf(v.y));
            h[1] = __floats2half2_rn(eluf(v.z), eluf(v.w));
            ((uint2*)g_xt)[i] = *(uint2*)h;
        } else {
            ((float4*)dst)[i] = v;
        }
    }
}

// ---------------------------------------------------------------------------
extern "C" void kernel_launch(void* const* d_in, const int* in_sizes, int n_in,
                              void* d_out, int out_size) {
    const float* gi  = (const float*)d_in[0];
    const float* xin = (const float*)d_in[1];
    const float* Wg0 = (const float*)d_in[2];
    const float* bg0 = (const float*)d_in[3];
    const float* Wg1 = (const float*)d_in[4];
    const float* bg1 = (const float*)d_in[5];
    const float* Wgo = (const float*)d_in[6];
    const float* bgo = (const float*)d_in[7];
    const float* a0  = (const float*)d_in[8];
    const float* be0 = (const float*)d_in[9];
    const float* a1  = (const float*)d_in[10];
    const float* be1 = (const float*)d_in[11];
    const float* a2  = (const float*)d_in[12];
    const float* be2 = (const float*)d_in[13];
    float* out = (float*)d_out;

    static int init_done = 0;
    if (!init_done) {
        cudaFuncSetAttribute(gemm_kernel, cudaFuncAttributeMaxDynamicSharedMemorySize, SMEM_BYTES);
        init_done = 1;
    }

    __half* d_xt; cudaGetSymbolAddress((void**)&d_xt, g_xt);
    __half* d_al; cudaGetSymbolAddress((void**)&d_al, g_alpha);

    gating_kernel<<<B_ROWS / 8, 128>>>(gi, Wg0, bg0, Wg1, bg1, Wgo, bgo);
    cvt_half_kernel<<<256, 256>>>(xin, d_xt, B_ROWS * XDIM / 8);

    dim3 grid(XDIM / BN, B_ROWS / BM, 2);   // (8, 32, 2) = 512 CTAs

    // layer 0
    cvt_half_kernel<<<1024, 256>>>(a0, d_al, NE * XDIM * XDIM / 8);
    gemm_kernel<<<grid, 128, SMEM_BYTES>>>(be0);
    reduce_kernel<<<1024, 256>>>(nullptr, 1);
    // layer 1
    cvt_half_kernel<<<1024, 256>>>(a1, d_al, NE * XDIM * XDIM / 8);
    gemm_kernel<<<grid, 128, SMEM_BYTES>>>(be1);
    reduce_kernel<<<1024, 256>>>(nullptr, 1);
    // layer 2
    cvt_half_kernel<<<1024, 256>>>(a2, d_al, NE * XDIM * XDIM / 8);
    gemm_kernel<<<grid, 128, SMEM_BYTES>>>(be2);
    reduce_kernel<<<1024, 256>>>(out, 0);
}

// round 14
// speedup vs baseline: 1.0119x; 1.0119x over previous
#include <cuda_runtime.h>
#include <cuda_fp16.h>
#include <math.h>
#include <stdint.h>

#define B_ROWS 2048
#define GIN    128
#define GH     128
#define NE     8
#define XDIM   512

// Static scratch (allocation-free rule)
__device__ __align__(16) float  g_gate[B_ROWS * NE];
__device__ __align__(16) __half g_xt[(size_t)B_ROWS * XDIM];           // fp16 activations
__device__ __align__(16) __half g_alpha[(size_t)NE * XDIM * XDIM];     // fp16 weights (4 MB)
__device__ __align__(16) float  g_part[8ull * B_ROWS * XDIM];          // per-expert partials (32 MB)

__device__ __forceinline__ float eluf(float x) { return x > 0.0f ? x : expm1f(x); }

// ---------------------------------------------------------------------------
// Gating network (validated R1-R12)
// ---------------------------------------------------------------------------
__global__ __launch_bounds__(128) void gating_kernel(
    const float* __restrict__ GI,
    const float* __restrict__ Wg0, const float* __restrict__ bg0,
    const float* __restrict__ Wg1, const float* __restrict__ bg1,
    const float* __restrict__ Wgo, const float* __restrict__ bgo)
{
    __shared__ float sx[8][GIN];
    __shared__ float sh[8][GH];
    __shared__ float sl[8][NE];

    const int r0  = blockIdx.x * 8;
    const int tid = threadIdx.x;

    for (int idx = tid; idx < 8 * GIN; idx += 128)
        sx[idx >> 7][idx & 127] = GI[(size_t)(r0 + (idx >> 7)) * GIN + (idx & 127)];
    __syncthreads();

    float acc[8];
    #pragma unroll
    for (int r = 0; r < 8; r++) acc[r] = bg0[tid];
    #pragma unroll 4
    for (int i = 0; i < GIN; i++) {
        float w = Wg0[i * GH + tid];
        #pragma unroll
        for (int r = 0; r < 8; r++) acc[r] += sx[r][i] * w;
    }
    #pragma unroll
    for (int r = 0; r < 8; r++) sh[r][tid] = eluf(acc[r]);
    __syncthreads();

    #pragma unroll
    for (int r = 0; r < 8; r++) acc[r] = bg1[tid];
    #pragma unroll 4
    for (int i = 0; i < GH; i++) {
        float w = Wg1[i * GH + tid];
        #pragma unroll
        for (int r = 0; r < 8; r++) acc[r] += sh[r][i] * w;
    }
    __syncthreads();
    #pragma unroll
    for (int r = 0; r < 8; r++) sx[r][tid] = eluf(acc[r]);
    __syncthreads();

    if (tid < 64) {
        const int r = tid >> 3, e = tid & 7;
        float a = bgo[e];
        #pragma unroll 4
        for (int i = 0; i < GH; i++) a += sx[r][i] * Wgo[i * NE + e];
        sl[r][e] = a;
    }
    __syncthreads();

    if (tid < 8) {
        const int r = tid;
        float mx = sl[r][0];
        #pragma unroll
        for (int e = 1; e < NE; e++) mx = fmaxf(mx, sl[r][e]);
        float ex[NE], s = 0.0f;
        #pragma unroll
        for (int e = 0; e < NE; e++) { ex[e] = expf(sl[r][e] - mx); s += ex[e]; }
        float inv = 1.0f / s;
        #pragma unroll
        for (int e = 0; e < NE; e++)
            g_gate[(size_t)(r0 + r) * NE + e] = ex[e] * inv;
    }
}

// float -> half conversion (8 elems per thread-iter)
__global__ __launch_bounds__(256) void cvt_half_kernel(
    const float* __restrict__ src, __half* __restrict__ dst, int n8)
{
    for (int i = blockIdx.x * 256 + threadIdx.x; i < n8; i += gridDim.x * 256) {
        float4 v0 = ((const float4*)src)[2 * i];
        float4 v1 = ((const float4*)src)[2 * i + 1];
        __half2 h[4];
        h[0] = __floats2half2_rn(v0.x, v0.y);
        h[1] = __floats2half2_rn(v0.z, v0.w);
        h[2] = __floats2half2_rn(v1.x, v1.y);
        h[3] = __floats2half2_rn(v1.z, v1.w);
        ((uint4*)dst)[i] = *(uint4*)h;
    }
}

// ---------------------------------------------------------------------------
// fp16 GEMM: one expert per CTA (blockIdx.z), K = 512 per CTA.
// Tile 128x128, 4 warps, warptile 64x64, BK=64 halves, NST=2 cp.async.
// Epilogue: partial[z][b,n] = g_e[b] * (acc + beta_e[n])   (fp32)
// ---------------------------------------------------------------------------
#define BM 128
#define BN 128
#define BKH 64
#define NKT 8                          // 512 / 64
#define PADH 72                        // half stride per row (144 B)
#define STG_H ((BM + BN) * PADH)       // 18432 halves per stage
#define STG_B (STG_H * 2)              // 36864 B
#define NST 2
#define SMEM_BYTES (NST * STG_B + BN * 4)   // 74240

__device__ __forceinline__ void cp16(uint32_t dst, const void* src) {
    asm volatile("cp.async.cg.shared.global [%0], [%1], 16;"
                 :: "r"(dst), "l"(__cvta_generic_to_global(src)) : "memory");
}
__device__ __forceinline__ void ldmx4(uint32_t* r, uint32_t addr) {
    asm volatile("ldmatrix.sync.aligned.m8n8.x4.shared.b16 {%0,%1,%2,%3}, [%4];"
                 : "=r"(r[0]), "=r"(r[1]), "=r"(r[2]), "=r"(r[3]) : "r"(addr));
}
__device__ __forceinline__ void mma16(float* c, const uint32_t* a, const uint32_t* b) {
    asm volatile(
        "mma.sync.aligned.m16n8k16.row.col.f32.f16.f16.f32 "
        "{%0,%1,%2,%3}, {%4,%5,%6,%7}, {%8,%9}, {%0,%1,%2,%3};"
        : "+f"(c[0]), "+f"(c[1]), "+f"(c[2]), "+f"(c[3])
        : "r"(a[0]), "r"(a[1]), "r"(a[2]), "r"(a[3]), "r"(b[0]), "r"(b[1]));
}

__global__ __launch_bounds__(128, 3) void gemm_kernel(const float* __restrict__ beta)
{
    extern __shared__ __half smem[];
    float* sbeta = (float*)(smem + NST * STG_H);   // [128]

    const int tid  = threadIdx.x;
    const int wid  = tid >> 5, lane = tid & 31;
    const int qid  = lane >> 2, qk = lane & 3;
    const int wm   = (wid & 1) * 64;
    const int wn   = (wid >> 1) * 64;
    const int n0   = blockIdx.x * BN;
    const int m0   = blockIdx.y * BM;
    const int e    = blockIdx.z;

    const uint32_t smem_u = (uint32_t)__cvta_generic_to_shared(smem);

    const int lr   = lane & 15;
    const int lkB8 = (lane >> 4) * 8;

    const __half* Abase = g_xt + (size_t)m0 * XDIM;
    const __half* Bbase = g_alpha + ((size_t)e * XDIM + n0) * XDIM;

    auto load_chunk = [&](int s, int c) {
        const int i0 = c * BKH;
        const __half* Ab = Abase + i0;
        const __half* Bb = Bbase + i0;
        const uint32_t sa  = smem_u + s * STG_B;
        const uint32_t sbm = sa + BM * PADH * 2;
        #pragma unroll
        for (int i = 0; i < 8; i++) {          // A: 128 rows x 8 x16B
            int unit = i * 128 + tid;
            int row = unit >> 3, c16 = unit & 7;
            cp16(sa + row * (PADH * 2) + c16 * 16, Ab + (size_t)row * XDIM + c16 * 8);
        }
        #pragma unroll
        for (int i = 0; i < 8; i++) {          // B: 128 rows x 8 x16B
            int unit = i * 128 + tid;
            int row = unit >> 3, c16 = unit & 7;
            cp16(sbm + row * (PADH * 2) + c16 * 16, Bb + (size_t)row * XDIM + c16 * 8);
        }
    };

    load_chunk(0, 0);
    asm volatile("cp.async.commit_group;" ::: "memory");
    load_chunk(1, 1);
    asm volatile("cp.async.commit_group;" ::: "memory");

    if (tid < 128) sbeta[tid] = beta[(size_t)e * XDIM + n0 + tid];

    float c[4][8][4];
    #pragma unroll
    for (int mt = 0; mt < 4; mt++)
        #pragma unroll
        for (int nt = 0; nt < 8; nt++)
            #pragma unroll
            for (int j = 0; j < 4; j++) c[mt][nt][j] = 0.0f;

    // hoisted per-lane fragment base offsets (bytes)
    const uint32_t aOff = ((wm + lr) * PADH + lkB8) * 2;
    const uint32_t bOff = ((wn + lr) * PADH + lkB8) * 2 + BM * PADH * 2;

    for (int kt = 0; kt < NKT; kt++) {
        asm volatile("cp.async.wait_group 1;" ::: "memory");
        __syncthreads();

        const uint32_t stg = smem_u + (kt & 1) * STG_B;
        const uint32_t aB = stg + aOff;
        const uint32_t bB = stg + bOff;

        #pragma unroll
        for (int ks = 0; ks < 4; ks++) {
            uint32_t a[4][4], b[8][2];
            #pragma unroll
            for (int mt = 0; mt < 4; mt++)
                ldmx4(a[mt], aB + (mt * 16 * PADH + ks * 16) * 2);
            #pragma unroll
            for (int p = 0; p < 4; p++) {
                uint32_t r[4];
                ldmx4(r, bB + (p * 16 * PADH + ks * 16) * 2);
                b[2 * p][0]     = r[0]; b[2 * p + 1][0] = r[1];
                b[2 * p][1]     = r[2]; b[2 * p + 1][1] = r[3];
            }
            #pragma unroll
            for (int mt = 0; mt < 4; mt++)
                #pragma unroll
                for (int nt = 0; nt < 8; nt++)
                    mma16(c[mt][nt], a[mt], b[nt]);
        }

        __syncthreads();
        if (kt + 2 < NKT) load_chunk(kt & 1, kt + 2);
        asm volatile("cp.async.commit_group;" ::: "memory");
    }

    // epilogue: partial = g_e * (acc + beta_e)
    float* P = g_part + (size_t)e * B_ROWS * XDIM;
    #pragma unroll
    for (int mt = 0; mt < 4; mt++) {
        const int r0 = wm + mt * 16 + qid, r1 = r0 + 8;
        const float g0 = g_gate[(size_t)(m0 + r0) * NE + e];
        const float g1 = g_gate[(size_t)(m0 + r1) * NE + e];
        #pragma unroll
        for (int nt = 0; nt < 8; nt++) {
            const int cc = wn + nt * 8 + 2 * qk;
            const float bx = sbeta[cc], by = sbeta[cc + 1];
            float2 o0, o1;
            o0.x = g0 * (c[mt][nt][0] + bx);
            o0.y = g0 * (c[mt][nt][1] + by);
            o1.x = g1 * (c[mt][nt][2] + bx);
            o1.y = g1 * (c[mt][nt][3] + by);
            *(float2*)(P + (size_t)(m0 + r0) * XDIM + n0 + cc) = o0;
            *(float2*)(P + (size_t)(m0 + r1) * XDIM + n0 + cc) = o1;
        }
    }
}

// Sum 8 partials; mode 1: ELU -> half -> g_xt; mode 0: raw fp32 -> dst
__global__ __launch_bounds__(256) void reduce_kernel(float* __restrict__ dst, int mode)
{
    const int n4 = B_ROWS * XDIM / 4;
    for (int i = blockIdx.x * 256 + threadIdx.x; i < n4; i += gridDim.x * 256) {
        float4 v = ((const float4*)g_part)[i];
        #pragma unroll
        for (int z = 1; z < 8; z++) {
            float4 p = ((const float4*)(g_part + (size_t)z * B_ROWS * XDIM))[i];
            v.x += p.x; v.y += p.y; v.z += p.z; v.w += p.w;
        }
        if (mode == 1) {
            __half2 h[2];
            h[0] = __floats2half2_rn(eluf(v.x), eluf(v.y));
            h[1] = __floats2half2_rn(eluf(v.z), eluf(v.w));
            ((uint2*)g_xt)[i] = *(uint2*)h;
        } else {
            ((float4*)dst)[i] = v;
        }
    }
}

// ---------------------------------------------------------------------------
extern "C" void kernel_launch(void* const* d_in, const int* in_sizes, int n_in,
                              void* d_out, int out_size) {
    const float* gi  = (const float*)d_in[0];
    const float* xin = (const float*)d_in[1];
    const float* Wg0 = (const float*)d_in[2];
    const float* bg0 = (const float*)d_in[3];
    const float* Wg1 = (const float*)d_in[4];
    const float* bg1 = (const float*)d_in[5];
    const float* Wgo = (const float*)d_in[6];
    const float* bgo = (const float*)d_in[7];
    const float* a0  = (const float*)d_in[8];
    const float* be0 = (const float*)d_in[9];
    const float* a1  = (const float*)d_in[10];
    const float* be1 = (const float*)d_in[11];
    const float* a2  = (const float*)d_in[12];
    const float* be2 = (const float*)d_in[13];
    float* out = (float*)d_out;

    static int init_done = 0;
    if (!init_done) {
        cudaFuncSetAttribute(gemm_kernel, cudaFuncAttributeMaxDynamicSharedMemorySize, SMEM_BYTES);
        init_done = 1;
    }

    __half* d_xt; cudaGetSymbolAddress((void**)&d_xt, g_xt);
    __half* d_al; cudaGetSymbolAddress((void**)&d_al, g_alpha);

    gating_kernel<<<B_ROWS / 8, 128>>>(gi, Wg0, bg0, Wg1, bg1, Wgo, bgo);
    cvt_half_kernel<<<256, 256>>>(xin, d_xt, B_ROWS * XDIM / 8);

    dim3 grid(XDIM / BN, B_ROWS / BM, NE);   // (4, 16, 8) = 512 CTAs

    // layer 0
    cvt_half_kernel<<<1024, 256>>>(a0, d_al, NE * XDIM * XDIM / 8);
    gemm_kernel<<<grid, 128, SMEM_BYTES>>>(be0);
    reduce_kernel<<<1024, 256>>>(nullptr, 1);
    // layer 1
    cvt_half_kernel<<<1024, 256>>>(a1, d_al, NE * XDIM * XDIM / 8);
    gemm_kernel<<<grid, 128, SMEM_BYTES>>>(be1);
    reduce_kernel<<<1024, 256>>>(nullptr, 1);
    // layer 2
    cvt_half_kernel<<<1024, 256>>>(a2, d_al, NE * XDIM * XDIM / 8);
    gemm_kernel<<<grid, 128, SMEM_BYTES>>>(be2);
    reduce_kernel<<<1024, 256>>>(out, 0);
}